// round 14
// baseline (speedup 1.0000x reference)
#include <cuda_runtime.h>
#include <cuda_fp16.h>
#include <math.h>
#include <stdint.h>

#define NN 100000
#define NE 1600000
#define NP 500000
#define SCAN_B 1024
#define NBLK ((NN + SCAN_B - 1) / SCAN_B)   // 98

// ---------------- static device scratch ----------------
__device__ float  g_selfb[(size_t)NN * 128];  // selfb; reused as U after layer 3
__device__ float  g_v[(size_t)NN * 128];      // V = Z @ W1_bot
__device__ __half g_suph[(size_t)NN * 128];   // h @ Wn in fp16 (gathered operand)
__device__ __half g_ahi[(size_t)NN * 128];    // activation hi
__device__ __half g_alo[(size_t)NN * 128];    // activation lo
__device__ int   g_rowptr[NN + 1];
__device__ int   g_cursor[NN];
__device__ int   g_partial[NBLK];
__device__ int   g_blockoff[NBLK];
__device__ int   g_pcol[NE];
__device__ float g_pw[NE];
// converted weights (all [n][k128] layout, fp16 hi only):
// mats 0..5 = layer ws/wn pairs, 6,7 = W1_top/W1_bot
#define W_TOTAL (8 * 16384)
__device__ __half g_whi[W_TOTAL];

#define PK128 136

// ---------------- helpers ----------------
__device__ __forceinline__ uint32_t smem_u32(const void* p) {
    uint32_t a;
    asm("{ .reg .u64 t; cvta.to.shared.u64 t, %1; cvt.u32.u64 %0, t; }" : "=r"(a) : "l"(p));
    return a;
}
__device__ __forceinline__ void ldsm_x4(uint32_t& r0, uint32_t& r1, uint32_t& r2, uint32_t& r3,
                                        uint32_t addr) {
    asm volatile("ldmatrix.sync.aligned.m8n8.x4.shared.b16 {%0,%1,%2,%3}, [%4];"
                 : "=r"(r0), "=r"(r1), "=r"(r2), "=r"(r3) : "r"(addr));
}
__device__ __forceinline__ void ldsm_x2(uint32_t& r0, uint32_t& r1, uint32_t addr) {
    asm volatile("ldmatrix.sync.aligned.m8n8.x2.shared.b16 {%0,%1}, [%2];"
                 : "=r"(r0), "=r"(r1) : "r"(addr));
}
__device__ __forceinline__ void mma16816(float* c, const uint32_t* a, const uint32_t* b) {
    asm volatile("mma.sync.aligned.m16n8k16.row.col.f32.f16.f16.f32 "
                 "{%0,%1,%2,%3}, {%4,%5,%6,%7}, {%8,%9}, {%0,%1,%2,%3};"
                 : "+f"(c[0]), "+f"(c[1]), "+f"(c[2]), "+f"(c[3])
                 : "r"(a[0]), "r"(a[1]), "r"(a[2]), "r"(a[3]), "r"(b[0]), "r"(b[1]));
}
__device__ __forceinline__ void cp16(uint32_t dst, const void* src, unsigned sz) {
    asm volatile("cp.async.cg.shared.global [%0], [%1], 16, %2;"
                 :: "r"(dst), "l"(src), "r"(sz) : "memory");
}
#define CP_COMMIT() asm volatile("cp.async.commit_group;" ::: "memory")
#define CP_WAIT1()  asm volatile("cp.async.wait_group 1;" ::: "memory")

__device__ __forceinline__ void split1(float v, __half& h, __half& l) {
    h = __float2half_rn(v);
    l = __float2half_rn(v - __half2float(h));
}

// ---------------- CSR build ----------------
__global__ void k_zero_deg() {
    int i = blockIdx.x * blockDim.x + threadIdx.x;
    if (i < NN) g_cursor[i] = 0;
}
__global__ void k_count_deg(const int* __restrict__ row) {
    int e = blockIdx.x * blockDim.x + threadIdx.x;
    if (e < NE) atomicAdd(&g_cursor[row[e]], 1);
}
__global__ __launch_bounds__(SCAN_B) void k_scan_part() {
    __shared__ int sh[SCAN_B / 32];
    int t = threadIdx.x;
    int idx = blockIdx.x * SCAN_B + t;
    int v = (idx < NN) ? g_cursor[idx] : 0;
#pragma unroll
    for (int off = 16; off > 0; off >>= 1) v += __shfl_down_sync(0xffffffffu, v, off);
    if ((t & 31) == 0) sh[t >> 5] = v;
    __syncthreads();
    if (t < 32) {
        int s = (t < SCAN_B / 32) ? sh[t] : 0;
#pragma unroll
        for (int off = 16; off > 0; off >>= 1) s += __shfl_down_sync(0xffffffffu, s, off);
        if (t == 0) g_partial[blockIdx.x] = s;
    }
}
__global__ __launch_bounds__(128) void k_scan_mid() {
    __shared__ int sh[128];
    int t = threadIdx.x;
    int v = (t < NBLK) ? g_partial[t] : 0;
    sh[t] = v;
    __syncthreads();
#pragma unroll
    for (int off = 1; off < 128; off <<= 1) {
        int y = (t >= off) ? sh[t - off] : 0;
        __syncthreads();
        sh[t] += y;
        __syncthreads();
    }
    if (t < NBLK) g_blockoff[t] = sh[t] - v;
}
__global__ __launch_bounds__(SCAN_B) void k_scan_final() {
    __shared__ int sh[SCAN_B];
    int t = threadIdx.x;
    int idx = blockIdx.x * SCAN_B + t;
    int v = (idx < NN) ? g_cursor[idx] : 0;
    sh[t] = v;
    __syncthreads();
#pragma unroll
    for (int off = 1; off < SCAN_B; off <<= 1) {
        int y = (t >= off) ? sh[t - off] : 0;
        __syncthreads();
        sh[t] += y;
        __syncthreads();
    }
    if (idx < NN) {
        int incl = sh[t] + g_blockoff[blockIdx.x];
        g_rowptr[idx + 1] = incl;
        g_cursor[idx] = incl - v;
    }
    if (idx == 0) g_rowptr[0] = 0;
}
__global__ void k_scatter_edges(const int* __restrict__ row, const int* __restrict__ col,
                                const float* __restrict__ w) {
    int e = blockIdx.x * blockDim.x + threadIdx.x;
    if (e < NE) {
        int pos = atomicAdd(&g_cursor[row[e]], 1);
        g_pcol[pos] = col[e];
        g_pw[pos]   = w[e];
    }
}

// ---------------- converters ----------------
__global__ void k_convert_x(const float* __restrict__ x) {
    int i = blockIdx.x * blockDim.x + threadIdx.x;
    if (i < NN * 32) {
        float4 v = *(const float4*)(x + (size_t)i * 4);
        __half h0, h1, h2, h3, l0, l1, l2, l3;
        split1(v.x, h0, l0); split1(v.y, h1, l1);
        split1(v.z, h2, l2); split1(v.w, h3, l3);
        __half2 H01 = __halves2half2(h0, h1), H23 = __halves2half2(h2, h3);
        __half2 L01 = __halves2half2(l0, l1), L23 = __halves2half2(l2, l3);
        uint2 uh, ul;
        uh.x = *reinterpret_cast<unsigned*>(&H01); uh.y = *reinterpret_cast<unsigned*>(&H23);
        ul.x = *reinterpret_cast<unsigned*>(&L01); ul.y = *reinterpret_cast<unsigned*>(&L23);
        *(uint2*)(g_ahi + (size_t)i * 4) = uh;
        *(uint2*)(g_alo + (size_t)i * 4) = ul;
    }
}
__global__ void k_convert_weights(const float* w0, const float* w1_, const float* w2_,
                                  const float* w3, const float* w4, const float* w5,
                                  const float* wdec) {
    int idx = blockIdx.x * blockDim.x + threadIdx.x;
    if (idx >= W_TOTAL) return;
    int m = idx >> 14;
    int e = idx & 16383;
    int n = e >> 7, k = e & 127;
    float v;
    if (m < 6) {
        const float* W = (m == 0) ? w0 : (m == 1) ? w1_ : (m == 2) ? w2_
                       : (m == 3) ? w3 : (m == 4) ? w4 : w5;
        v = W[k * 128 + n];
    } else {
        v = wdec[((m - 6) * 128 + k) * 128 + n];
    }
    g_whi[idx] = __float2half_rn(v);
}

// ---------------- neighbor aggregation: warp-per-node, 8B vector gathers ----------------
__global__ __launch_bounds__(128) void k_aggregate(float* __restrict__ outf, int relu, int writef) {
    int warp = threadIdx.x >> 5;
    int lane = threadIdx.x & 31;
    int node = blockIdx.x * 4 + warp;
    if (node >= NN) return;
    size_t base = (size_t)node * 128 + lane * 4;

    float4 sv = *(const float4*)(g_selfb + base);
    float a0 = sv.x, a1 = sv.y, a2 = sv.z, a3 = sv.w;

    int s = g_rowptr[node];
    int e = g_rowptr[node + 1];
    for (int i0 = s; i0 < e; i0 += 32) {
        int n = e - i0;
        if (n > 32) n = 32;
        int   c  = 0;
        float wv = 0.f;
        if (lane < n) { c = g_pcol[i0 + lane]; wv = g_pw[i0 + lane]; }
        for (int j = 0; j < n; j++) {
            int   cj = __shfl_sync(0xffffffffu, c, j);
            float wj = __shfl_sync(0xffffffffu, wv, j);
            uint2 hv = *(const uint2*)(g_suph + (size_t)cj * 128 + lane * 4);
            __half2 h01 = *reinterpret_cast<__half2*>(&hv.x);
            __half2 h23 = *reinterpret_cast<__half2*>(&hv.y);
            float2 f01 = __half22float2(h01);
            float2 f23 = __half22float2(h23);
            a0 += wj * f01.x; a1 += wj * f01.y;
            a2 += wj * f23.x; a3 += wj * f23.y;
        }
    }
    if (relu) {
        a0 = fmaxf(a0, 0.f); a1 = fmaxf(a1, 0.f);
        a2 = fmaxf(a2, 0.f); a3 = fmaxf(a3, 0.f);
    }
    if (writef) *(float4*)(outf + base) = make_float4(a0, a1, a2, a3);
    __half h0, h1, h2, h3, l0, l1, l2, l3;
    split1(a0, h0, l0); split1(a1, h1, l1);
    split1(a2, h2, l2); split1(a3, h3, l3);
    __half2 H01 = __halves2half2(h0, h1), H23 = __halves2half2(h2, h3);
    __half2 L01 = __halves2half2(l0, l1), L23 = __halves2half2(l2, l3);
    uint2 uh, ul;
    uh.x = *reinterpret_cast<unsigned*>(&H01); uh.y = *reinterpret_cast<unsigned*>(&H23);
    ul.x = *reinterpret_cast<unsigned*>(&L01); ul.y = *reinterpret_cast<unsigned*>(&L23);
    *(uint2*)(g_ahi + base) = uh;
    *(uint2*)(g_alo + base) = ul;
}

// ---------------- shared GEMM plumbing ----------------
#define NODE_TILES ((NN + 63) / 64)              // 1563
#define NO_ASTG  (64 * PK128 * 2)                // 17408
#define NO_STAGE (2 * NO_ASTG)                   // 34816 per stage (hi+lo)

__device__ __forceinline__ void issue_node_tile(int rowBase, uint32_t smHi, uint32_t smLo, int tid) {
    int r = tid >> 3;               // 0..63
    int u0 = (tid & 7) * 2;         // units 0..15
    long long gr = (long long)rowBase + r;
    unsigned sz = (gr < NN) ? 16u : 0u;
    long long grc = gr < NN ? gr : (NN - 1);
    const char* srcH = (const char*)g_ahi + grc * 256;
    const char* srcL = (const char*)g_alo + grc * 256;
    uint32_t drow = (uint32_t)r * (PK128 * 2);
#pragma unroll
    for (int q = 0; q < 2; q++) {
        uint32_t o = (u0 + q) * 16;
        cp16(smHi + drow + o, srcH + o, sz);
        cp16(smLo + drow + o, srcL + o, sz);
    }
}

// ---------------- persistent node GEMM: 512 thr, mat-split warps, 3-stage, 2-term both mats ----------------
#define NO_BIAS  0                               // 512
#define NO_WSHI  1024
#define NO_WNHI  (NO_WSHI + 128 * PK128 * 2)     // +34816
#define NO_A0    (NO_WNHI + 128 * PK128 * 2)
#define NO_SMEM  (NO_A0 + 3 * NO_STAGE)          // 175104

__global__ __launch_bounds__(512, 1) void k_mm_node(
    int wsel, const float* __restrict__ bias, float* __restrict__ Cself)
{
    extern __shared__ char sm[];
    uint32_t sb = smem_u32(sm);
    int tid = threadIdx.x;
    int lane = tid & 31, w = tid >> 5;
    int mat   = w & 1;            // 0 = self, 1 = support
    int warpN = (w >> 1) & 3;
    int warpM = (w >> 3) & 1;

    if (tid < 128) ((float*)(sm + NO_BIAS))[tid] = bias[tid];
    {
        const uint4* whS = (const uint4*)(g_whi + (size_t)(2 * wsel) * 16384);
        const uint4* whN = (const uint4*)(g_whi + (size_t)(2 * wsel + 1) * 16384);
        for (int idx = tid; idx < 2048; idx += 512) {
            int r = idx >> 4, u = idx & 15;
            uint32_t off = r * (PK128 * 2) + u * 16;
            *(uint4*)(sm + NO_WSHI + off) = whS[idx];
            *(uint4*)(sm + NO_WNHI + off) = whN[idx];
        }
    }

    uint32_t stg[3] = { sb + NO_A0, sb + NO_A0 + NO_STAGE, sb + NO_A0 + 2 * NO_STAGE };
    const float* sbias = (const float*)(sm + NO_BIAS);

    uint32_t aRow = warpM * 32 + (lane & 15);
    uint32_t aColSel = (lane >> 4) * 8;
    uint32_t aOff0 = (aRow * PK128 + aColSel) * 2;
    uint32_t aOff1 = ((aRow + 16) * PK128 + aColSel) * 2;
    uint32_t bRow = warpN * 32 + (lane & 7);
    uint32_t bColSel = ((lane >> 3) & 1) * 8;
    uint32_t bOffBase = (bRow * PK128 + bColSel) * 2;
    uint32_t bHiBase = (mat ? (sb + NO_WNHI) : (sb + NO_WSHI)) + bOffBase;

    int g = gridDim.x;
    int t = blockIdx.x;
    int s = 0;
    issue_node_tile(t * 64, stg[0], stg[0] + NO_ASTG, tid);
    CP_COMMIT();
    issue_node_tile((t + g) * 64, stg[1], stg[1] + NO_ASTG, tid);
    CP_COMMIT();
    __syncthreads();

    while (t < NODE_TILES) {
        CP_WAIT1();
        __syncthreads();

        int s2i = (s >= 1) ? (s - 1) : 2;   // == (s+2)%3
        issue_node_tile((t + 2 * g) * 64, stg[s2i], stg[s2i] + NO_ASTG, tid);
        CP_COMMIT();

        float acc[2][4][4];
#pragma unroll
        for (int mt = 0; mt < 2; mt++)
#pragma unroll
            for (int nt = 0; nt < 4; nt++)
#pragma unroll
                for (int q = 0; q < 4; q++) acc[mt][nt][q] = 0.f;

        uint32_t asH = stg[s], asL = stg[s] + NO_ASTG;
#pragma unroll
        for (int ks = 0; ks < 8; ks++) {
            uint32_t kadd = ks * 32;
            uint32_t aH[2][4], aL[2][4];
            ldsm_x4(aH[0][0], aH[0][1], aH[0][2], aH[0][3], asH + aOff0 + kadd);
            ldsm_x4(aH[1][0], aH[1][1], aH[1][2], aH[1][3], asH + aOff1 + kadd);
            ldsm_x4(aL[0][0], aL[0][1], aL[0][2], aL[0][3], asL + aOff0 + kadd);
            ldsm_x4(aL[1][0], aL[1][1], aL[1][2], aL[1][3], asL + aOff1 + kadd);
#pragma unroll
            for (int nt = 0; nt < 4; nt++) {
                uint32_t bo = nt * 8 * PK128 * 2 + kadd;
                uint32_t bH[2];
                ldsm_x2(bH[0], bH[1], bHiBase + bo);
                mma16816(acc[0][nt], aH[0], bH);
                mma16816(acc[1][nt], aH[1], bH);
                mma16816(acc[0][nt], aL[0], bH);
                mma16816(acc[1][nt], aL[1], bH);
            }
        }

        int base = t * 64;
        if (!mat) {
#pragma unroll
            for (int mt = 0; mt < 2; mt++) {
                int r0 = base + warpM * 32 + mt * 16 + (lane >> 2);
#pragma unroll
                for (int nt = 0; nt < 4; nt++) {
                    int c = warpN * 32 + nt * 8 + (lane & 3) * 2;
                    if (r0 < NN)
                        *(float2*)(Cself + (size_t)r0 * 128 + c) =
                            make_float2(acc[mt][nt][0] + sbias[c], acc[mt][nt][1] + sbias[c + 1]);
                    if (r0 + 8 < NN)
                        *(float2*)(Cself + (size_t)(r0 + 8) * 128 + c) =
                            make_float2(acc[mt][nt][2] + sbias[c], acc[mt][nt][3] + sbias[c + 1]);
                }
            }
        } else {
#pragma unroll
            for (int mt = 0; mt < 2; mt++) {
                int r0 = base + warpM * 32 + mt * 16 + (lane >> 2);
#pragma unroll
                for (int nt = 0; nt < 4; nt++) {
                    int c = warpN * 32 + nt * 8 + (lane & 3) * 2;
                    if (r0 < NN)
                        *(__half2*)(&g_suph[(size_t)r0 * 128 + c]) =
                            __halves2half2(__float2half_rn(acc[mt][nt][0]),
                                           __float2half_rn(acc[mt][nt][1]));
                    if (r0 + 8 < NN)
                        *(__half2*)(&g_suph[(size_t)(r0 + 8) * 128 + c]) =
                            __halves2half2(__float2half_rn(acc[mt][nt][2]),
                                           __float2half_rn(acc[mt][nt][3]));
                }
            }
        }
        t += g;
        s = (s + 1 == 3) ? 0 : (s + 1);
    }
}

// ---------------- persistent UV GEMM: U = Z@W1_top, V = Z@W1_bot (2-term, fp32 out) ----------------
#define NU_WTHI  0
#define NU_WBHI  (NU_WTHI + 128 * PK128 * 2)     // +34816
#define NU_A0    (NU_WBHI + 128 * PK128 * 2)
#define NU_SMEM  (NU_A0 + 3 * NO_STAGE)          // 174080

__global__ __launch_bounds__(512, 1) void k_mm_uv(float* __restrict__ U, float* __restrict__ V)
{
    extern __shared__ char sm[];
    uint32_t sb = smem_u32(sm);
    int tid = threadIdx.x;
    int lane = tid & 31, w = tid >> 5;
    int mat   = w & 1;            // 0 = U, 1 = V
    int warpN = (w >> 1) & 3;
    int warpM = (w >> 3) & 1;

    {
        const uint4* whT = (const uint4*)(g_whi + (size_t)6 * 16384);
        const uint4* whB = (const uint4*)(g_whi + (size_t)7 * 16384);
        for (int idx = tid; idx < 2048; idx += 512) {
            int r = idx >> 4, u = idx & 15;
            uint32_t off = r * (PK128 * 2) + u * 16;
            *(uint4*)(sm + NU_WTHI + off) = whT[idx];
            *(uint4*)(sm + NU_WBHI + off) = whB[idx];
        }
    }

    uint32_t stg[3] = { sb + NU_A0, sb + NU_A0 + NO_STAGE, sb + NU_A0 + 2 * NO_STAGE };

    uint32_t aRow = warpM * 32 + (lane & 15);
    uint32_t aColSel = (lane >> 4) * 8;
    uint32_t aOff0 = (aRow * PK128 + aColSel) * 2;
    uint32_t aOff1 = ((aRow + 16) * PK128 + aColSel) * 2;
    uint32_t bRow = warpN * 32 + (lane & 7);
    uint32_t bColSel = ((lane >> 3) & 1) * 8;
    uint32_t bOffBase = (bRow * PK128 + bColSel) * 2;
    uint32_t bHiBase = (mat ? (sb + NU_WBHI) : (sb + NU_WTHI)) + bOffBase;
    float* Cout = mat ? V : U;

    int g = gridDim.x;
    int t = blockIdx.x;
    int s = 0;
    issue_node_tile(t * 64, stg[0], stg[0] + NO_ASTG, tid);
    CP_COMMIT();
    issue_node_tile((t + g) * 64, stg[1], stg[1] + NO_ASTG, tid);
    CP_COMMIT();
    __syncthreads();

    while (t < NODE_TILES) {
        CP_WAIT1();
        __syncthreads();

        int s2i = (s >= 1) ? (s - 1) : 2;
        issue_node_tile((t + 2 * g) * 64, stg[s2i], stg[s2i] + NO_ASTG, tid);
        CP_COMMIT();

        float acc[2][4][4];
#pragma unroll
        for (int mt = 0; mt < 2; mt++)
#pragma unroll
            for (int nt = 0; nt < 4; nt++)
#pragma unroll
                for (int q = 0; q < 4; q++) acc[mt][nt][q] = 0.f;

        uint32_t asH = stg[s], asL = stg[s] + NO_ASTG;
#pragma unroll
        for (int ks = 0; ks < 8; ks++) {
            uint32_t kadd = ks * 32;
            uint32_t aH[2][4], aL[2][4];
            ldsm_x4(aH[0][0], aH[0][1], aH[0][2], aH[0][3], asH + aOff0 + kadd);
            ldsm_x4(aH[1][0], aH[1][1], aH[1][2], aH[1][3], asH + aOff1 + kadd);
            ldsm_x4(aL[0][0], aL[0][1], aL[0][2], aL[0][3], asL + aOff0 + kadd);
            ldsm_x4(aL[1][0], aL[1][1], aL[1][2], aL[1][3], asL + aOff1 + kadd);
#pragma unroll
            for (int nt = 0; nt < 4; nt++) {
                uint32_t bo = nt * 8 * PK128 * 2 + kadd;
                uint32_t bH[2];
                ldsm_x2(bH[0], bH[1], bHiBase + bo);
                mma16816(acc[0][nt], aH[0], bH);
                mma16816(acc[1][nt], aH[1], bH);
                mma16816(acc[0][nt], aL[0], bH);
                mma16816(acc[1][nt], aL[1], bH);
            }
        }

        int base = t * 64;
#pragma unroll
        for (int mt = 0; mt < 2; mt++) {
            int r0 = base + warpM * 32 + mt * 16 + (lane >> 2);
#pragma unroll
            for (int nt = 0; nt < 4; nt++) {
                int c = warpN * 32 + nt * 8 + (lane & 3) * 2;
                if (r0 < NN)
                    *(float2*)(Cout + (size_t)r0 * 128 + c) =
                        make_float2(acc[mt][nt][0], acc[mt][nt][1]);
                if (r0 + 8 < NN)
                    *(float2*)(Cout + (size_t)(r0 + 8) * 128 + c) =
                        make_float2(acc[mt][nt][2], acc[mt][nt][3]);
            }
        }
        t += g;
        s = (s + 1 == 3) ? 0 : (s + 1);
    }
}

// ---------------- decoder gather: p = sigmoid(relu(U[x]+V[y]+b1) . w2 + b2) ----------------
__global__ __launch_bounds__(128) void k_dec_gather(
    const float* __restrict__ U, const float* __restrict__ V,
    const int* __restrict__ xidx, const int* __restrict__ yidx,
    const float* __restrict__ b1, const float* __restrict__ w2, const float* __restrict__ b2,
    float* __restrict__ p)
{
    int warp = threadIdx.x >> 5;
    int lane = threadIdx.x & 31;
    int pp = blockIdx.x * 4 + warp;
    if (pp >= NP) return;
    int xn = xidx[pp], yn = yidx[pp];
    float4 u4 = *(const float4*)(U + (size_t)xn * 128 + lane * 4);
    float4 v4 = *(const float4*)(V + (size_t)yn * 128 + lane * 4);
    float4 b4 = *(const float4*)(b1 + lane * 4);
    float4 w4 = *(const float4*)(w2 + lane * 4);
    float s = fmaxf(u4.x + v4.x + b4.x, 0.f) * w4.x
            + fmaxf(u4.y + v4.y + b4.y, 0.f) * w4.y
            + fmaxf(u4.z + v4.z + b4.z, 0.f) * w4.z
            + fmaxf(u4.w + v4.w + b4.w, 0.f) * w4.w;
#pragma unroll
    for (int off = 16; off > 0; off >>= 1) s += __shfl_down_sync(0xffffffffu, s, off);
    if (lane == 0) {
        s += b2[0];
        p[pp] = 1.f / (1.f + expf(-s));
    }
}

// ---------------- launch ----------------
extern "C" void kernel_launch(void* const* d_in, const int* in_sizes, int n_in,
                              void* d_out, int out_size) {
    const float* x     = (const float*)d_in[0];
    const int*   erow  = (const int*)  d_in[1];
    const int*   ecol  = (const int*)  d_in[2];
    const float* ew    = (const float*)d_in[3];
    const int*   xidx  = (const int*)  d_in[4];
    const int*   yidx  = (const int*)  d_in[5];
    const float* ws[3] = { (const float*)d_in[6],  (const float*)d_in[9],  (const float*)d_in[12] };
    const float* wn[3] = { (const float*)d_in[7],  (const float*)d_in[10], (const float*)d_in[13] };
    const float* bb[3] = { (const float*)d_in[8],  (const float*)d_in[11], (const float*)d_in[14] };
    const float* dw1 = (const float*)d_in[15];
    const float* db1 = (const float*)d_in[16];
    const float* dw2 = (const float*)d_in[17];
    const float* db2 = (const float*)d_in[18];

    float* out = (float*)d_out;
    float* p_out = out;            // [NP]
    float* z_out = out + NP;       // [NN*128]

    void* ptr;
    cudaGetSymbolAddress(&ptr, g_selfb);   float* selfb_buf = (float*)ptr;  // doubles as U
    cudaGetSymbolAddress(&ptr, g_v);       float* v_buf     = (float*)ptr;

    int nsm = 148;
    cudaDeviceGetAttribute(&nsm, cudaDevAttrMultiProcessorCount, 0);

    cudaFuncSetAttribute(k_mm_node, cudaFuncAttributeMaxDynamicSharedMemorySize, NO_SMEM);
    cudaFuncSetAttribute(k_mm_uv,   cudaFuncAttributeMaxDynamicSharedMemorySize, NU_SMEM);

    // side stream for the CSR build (independent of converts + layer-1 GEMM)
    cudaStream_t s2;
    cudaStreamCreateWithFlags(&s2, cudaStreamNonBlocking);
    cudaEvent_t eFork, eJoin;
    cudaEventCreateWithFlags(&eFork, cudaEventDisableTiming);
    cudaEventCreateWithFlags(&eJoin, cudaEventDisableTiming);

    cudaEventRecord(eFork, 0);
    cudaStreamWaitEvent(s2, eFork, 0);

    const int aggGrid = (NN + 3) / 4;   // warp-per-node

    // main stream: converts + layer-1 GEMM (launch #4 overall = mm_node, for ncu)
    k_convert_x<<<(NN * 32 + 255) / 256, 256>>>(x);                                         // 1
    k_convert_weights<<<(W_TOTAL + 255) / 256, 256>>>(ws[0], wn[0], ws[1], wn[1], ws[2], wn[2], dw1); // 2
    k_zero_deg<<<(NN + 255) / 256, 256, 0, s2>>>();                                         // 3 (s2)
    k_mm_node<<<nsm, 512, NO_SMEM>>>(0, bb[0], selfb_buf);                                  // 4 <- profiled
    // CSR chain on s2
    k_count_deg<<<(NE + 255) / 256, 256, 0, s2>>>(erow);                                    // 5
    k_scan_part<<<NBLK, SCAN_B, 0, s2>>>();                                                 // 6
    k_scan_mid<<<1, 128, 0, s2>>>();                                                        // 7
    k_scan_final<<<NBLK, SCAN_B, 0, s2>>>();                                                // 8
    k_scatter_edges<<<(NE + 255) / 256, 256, 0, s2>>>(erow, ecol, ew);                      // 9
    cudaEventRecord(eJoin, s2);
    cudaStreamWaitEvent(0, eJoin, 0);

    k_aggregate<<<aggGrid, 128>>>(nullptr, 1, 0);                                           // 10
    k_mm_node<<<nsm, 512, NO_SMEM>>>(1, bb[1], selfb_buf);                                  // 11
    k_aggregate<<<aggGrid, 128>>>(nullptr, 1, 0);                                           // 12
    k_mm_node<<<nsm, 512, NO_SMEM>>>(2, bb[2], selfb_buf);                                  // 13
    k_aggregate<<<aggGrid, 128>>>(z_out, 0, 1);                                             // 14 (z + ahi/alo)
    // decoder: factored through W1
    k_mm_uv<<<nsm, 512, NU_SMEM>>>(selfb_buf, v_buf);                                       // 15 (U reuses selfb)
    k_dec_gather<<<(NP + 3) / 4, 128>>>(selfb_buf, v_buf, xidx, yidx, db1, dw2, db2, p_out);// 16
}

// round 15
// speedup vs baseline: 1.2780x; 1.2780x over previous
#include <cuda_runtime.h>
#include <cuda_fp16.h>
#include <math.h>
#include <stdint.h>

#define NN 100000
#define NE 1600000
#define NP 500000
#define SCAN_B 1024
#define NBLK ((NN + SCAN_B - 1) / SCAN_B)   // 98

// ---------------- static device scratch ----------------
__device__ float  g_selfb[(size_t)NN * 128];
__device__ __half g_suph[(size_t)NN * 128];   // h @ Wn fp16; reused as U (fp16) for decoder
__device__ __half g_vh[(size_t)NN * 128];     // V (fp16)
__device__ __half g_ahi[(size_t)NN * 128];    // activation hi
__device__ __half g_alo[(size_t)NN * 128];    // activation lo
__device__ int   g_rowptr[NN + 1];
__device__ int   g_cursor[NN];
__device__ int   g_partial[NBLK];
__device__ int   g_blockoff[NBLK];
__device__ int   g_pcol[NE];
__device__ float g_pw[NE];
// converted weights (all [n][k128] layout): mats 0..5 = layer ws/wn pairs, 6,7 = W1_top/W1_bot
#define W_TOTAL (8 * 16384)
__device__ __half g_whi[W_TOTAL];
__device__ __half g_wlo[W_TOTAL];

#define PK128 136

// ---------------- helpers ----------------
__device__ __forceinline__ uint32_t smem_u32(const void* p) {
    uint32_t a;
    asm("{ .reg .u64 t; cvta.to.shared.u64 t, %1; cvt.u32.u64 %0, t; }" : "=r"(a) : "l"(p));
    return a;
}
__device__ __forceinline__ void ldsm_x4(uint32_t& r0, uint32_t& r1, uint32_t& r2, uint32_t& r3,
                                        uint32_t addr) {
    asm volatile("ldmatrix.sync.aligned.m8n8.x4.shared.b16 {%0,%1,%2,%3}, [%4];"
                 : "=r"(r0), "=r"(r1), "=r"(r2), "=r"(r3) : "r"(addr));
}
__device__ __forceinline__ void ldsm_x2(uint32_t& r0, uint32_t& r1, uint32_t addr) {
    asm volatile("ldmatrix.sync.aligned.m8n8.x2.shared.b16 {%0,%1}, [%2];"
                 : "=r"(r0), "=r"(r1) : "r"(addr));
}
__device__ __forceinline__ void mma16816(float* c, const uint32_t* a, const uint32_t* b) {
    asm volatile("mma.sync.aligned.m16n8k16.row.col.f32.f16.f16.f32 "
                 "{%0,%1,%2,%3}, {%4,%5,%6,%7}, {%8,%9}, {%0,%1,%2,%3};"
                 : "+f"(c[0]), "+f"(c[1]), "+f"(c[2]), "+f"(c[3])
                 : "r"(a[0]), "r"(a[1]), "r"(a[2]), "r"(a[3]), "r"(b[0]), "r"(b[1]));
}
__device__ __forceinline__ void cp16(uint32_t dst, const void* src, unsigned sz) {
    asm volatile("cp.async.cg.shared.global [%0], [%1], 16, %2;"
                 :: "r"(dst), "l"(src), "r"(sz) : "memory");
}
#define CP_COMMIT() asm volatile("cp.async.commit_group;" ::: "memory")
#define CP_WAIT1()  asm volatile("cp.async.wait_group 1;" ::: "memory")

__device__ __forceinline__ void split1(float v, __half& h, __half& l) {
    h = __float2half_rn(v);
    l = __float2half_rn(v - __half2float(h));
}

// ---------------- CSR build ----------------
__global__ void k_zero_deg() {
    int i = blockIdx.x * blockDim.x + threadIdx.x;
    if (i < NN) g_cursor[i] = 0;
}
__global__ void k_count_deg(const int* __restrict__ row) {
    int e = blockIdx.x * blockDim.x + threadIdx.x;
    if (e < NE) atomicAdd(&g_cursor[row[e]], 1);
}
__global__ __launch_bounds__(SCAN_B) void k_scan_part() {
    __shared__ int sh[SCAN_B / 32];
    int t = threadIdx.x;
    int idx = blockIdx.x * SCAN_B + t;
    int v = (idx < NN) ? g_cursor[idx] : 0;
#pragma unroll
    for (int off = 16; off > 0; off >>= 1) v += __shfl_down_sync(0xffffffffu, v, off);
    if ((t & 31) == 0) sh[t >> 5] = v;
    __syncthreads();
    if (t < 32) {
        int s = (t < SCAN_B / 32) ? sh[t] : 0;
#pragma unroll
        for (int off = 16; off > 0; off >>= 1) s += __shfl_down_sync(0xffffffffu, s, off);
        if (t == 0) g_partial[blockIdx.x] = s;
    }
}
__global__ __launch_bounds__(128) void k_scan_mid() {
    __shared__ int sh[128];
    int t = threadIdx.x;
    int v = (t < NBLK) ? g_partial[t] : 0;
    sh[t] = v;
    __syncthreads();
#pragma unroll
    for (int off = 1; off < 128; off <<= 1) {
        int y = (t >= off) ? sh[t - off] : 0;
        __syncthreads();
        sh[t] += y;
        __syncthreads();
    }
    if (t < NBLK) g_blockoff[t] = sh[t] - v;
}
__global__ __launch_bounds__(SCAN_B) void k_scan_final() {
    __shared__ int sh[SCAN_B];
    int t = threadIdx.x;
    int idx = blockIdx.x * SCAN_B + t;
    int v = (idx < NN) ? g_cursor[idx] : 0;
    sh[t] = v;
    __syncthreads();
#pragma unroll
    for (int off = 1; off < SCAN_B; off <<= 1) {
        int y = (t >= off) ? sh[t - off] : 0;
        __syncthreads();
        sh[t] += y;
        __syncthreads();
    }
    if (idx < NN) {
        int incl = sh[t] + g_blockoff[blockIdx.x];
        g_rowptr[idx + 1] = incl;
        g_cursor[idx] = incl - v;
    }
    if (idx == 0) g_rowptr[0] = 0;
}
__global__ void k_scatter_edges(const int* __restrict__ row, const int* __restrict__ col,
                                const float* __restrict__ w) {
    int e = blockIdx.x * blockDim.x + threadIdx.x;
    if (e < NE) {
        int pos = atomicAdd(&g_cursor[row[e]], 1);
        g_pcol[pos] = col[e];
        g_pw[pos]   = w[e];
    }
}

// ---------------- converters ----------------
__global__ void k_convert_x(const float* __restrict__ x) {
    int i = blockIdx.x * blockDim.x + threadIdx.x;
    if (i < NN * 32) {
        float4 v = *(const float4*)(x + (size_t)i * 4);
        __half h0, h1, h2, h3, l0, l1, l2, l3;
        split1(v.x, h0, l0); split1(v.y, h1, l1);
        split1(v.z, h2, l2); split1(v.w, h3, l3);
        __half2 H01 = __halves2half2(h0, h1), H23 = __halves2half2(h2, h3);
        __half2 L01 = __halves2half2(l0, l1), L23 = __halves2half2(l2, l3);
        uint2 uh, ul;
        uh.x = *reinterpret_cast<unsigned*>(&H01); uh.y = *reinterpret_cast<unsigned*>(&H23);
        ul.x = *reinterpret_cast<unsigned*>(&L01); ul.y = *reinterpret_cast<unsigned*>(&L23);
        *(uint2*)(g_ahi + (size_t)i * 4) = uh;
        *(uint2*)(g_alo + (size_t)i * 4) = ul;
    }
}
__global__ void k_convert_weights(const float* w0, const float* w1_, const float* w2_,
                                  const float* w3, const float* w4, const float* w5,
                                  const float* wdec) {
    int idx = blockIdx.x * blockDim.x + threadIdx.x;
    if (idx >= W_TOTAL) return;
    int m = idx >> 14;
    int e = idx & 16383;
    int n = e >> 7, k = e & 127;
    float v;
    if (m < 6) {
        const float* W = (m == 0) ? w0 : (m == 1) ? w1_ : (m == 2) ? w2_
                       : (m == 3) ? w3 : (m == 4) ? w4 : w5;
        v = W[k * 128 + n];
    } else {
        v = wdec[((m - 6) * 128 + k) * 128 + n];
    }
    __half h, l;
    split1(v, h, l);
    g_whi[idx] = h;
    g_wlo[idx] = l;
}

// ---------------- neighbor aggregation: warp-per-node, 8B vector gathers ----------------
__global__ __launch_bounds__(128) void k_aggregate(float* __restrict__ outf, int relu, int writef) {
    int warp = threadIdx.x >> 5;
    int lane = threadIdx.x & 31;
    int node = blockIdx.x * 4 + warp;
    if (node >= NN) return;
    size_t base = (size_t)node * 128 + lane * 4;

    float4 sv = *(const float4*)(g_selfb + base);
    float a0 = sv.x, a1 = sv.y, a2 = sv.z, a3 = sv.w;

    int s = g_rowptr[node];
    int e = g_rowptr[node + 1];
    for (int i0 = s; i0 < e; i0 += 32) {
        int n = e - i0;
        if (n > 32) n = 32;
        int   c  = 0;
        float wv = 0.f;
        if (lane < n) { c = g_pcol[i0 + lane]; wv = g_pw[i0 + lane]; }
        for (int j = 0; j < n; j++) {
            int   cj = __shfl_sync(0xffffffffu, c, j);
            float wj = __shfl_sync(0xffffffffu, wv, j);
            uint2 hv = *(const uint2*)(g_suph + (size_t)cj * 128 + lane * 4);
            __half2 h01 = *reinterpret_cast<__half2*>(&hv.x);
            __half2 h23 = *reinterpret_cast<__half2*>(&hv.y);
            float2 f01 = __half22float2(h01);
            float2 f23 = __half22float2(h23);
            a0 += wj * f01.x; a1 += wj * f01.y;
            a2 += wj * f23.x; a3 += wj * f23.y;
        }
    }
    if (relu) {
        a0 = fmaxf(a0, 0.f); a1 = fmaxf(a1, 0.f);
        a2 = fmaxf(a2, 0.f); a3 = fmaxf(a3, 0.f);
    }
    if (writef) *(float4*)(outf + base) = make_float4(a0, a1, a2, a3);
    __half h0, h1, h2, h3, l0, l1, l2, l3;
    split1(a0, h0, l0); split1(a1, h1, l1);
    split1(a2, h2, l2); split1(a3, h3, l3);
    __half2 H01 = __halves2half2(h0, h1), H23 = __halves2half2(h2, h3);
    __half2 L01 = __halves2half2(l0, l1), L23 = __halves2half2(l2, l3);
    uint2 uh, ul;
    uh.x = *reinterpret_cast<unsigned*>(&H01); uh.y = *reinterpret_cast<unsigned*>(&H23);
    ul.x = *reinterpret_cast<unsigned*>(&L01); ul.y = *reinterpret_cast<unsigned*>(&L23);
    *(uint2*)(g_ahi + base) = uh;
    *(uint2*)(g_alo + base) = ul;
}

// ---------------- shared GEMM plumbing ----------------
#define NODE_TILES ((NN + 63) / 64)              // 1563
#define NO_ASTG  (64 * PK128 * 2)                // 17408
#define NO_STAGE (2 * NO_ASTG)                   // 34816 per stage (hi+lo)

__device__ __forceinline__ void issue_node_tile(int rowBase, uint32_t smHi, uint32_t smLo, int tid) {
    int r = tid >> 3;               // 0..63
    int u0 = (tid & 7) * 2;         // units 0..15
    long long gr = (long long)rowBase + r;
    unsigned sz = (gr < NN) ? 16u : 0u;
    long long grc = gr < NN ? gr : (NN - 1);
    const char* srcH = (const char*)g_ahi + grc * 256;
    const char* srcL = (const char*)g_alo + grc * 256;
    uint32_t drow = (uint32_t)r * (PK128 * 2);
#pragma unroll
    for (int q = 0; q < 2; q++) {
        uint32_t o = (u0 + q) * 16;
        cp16(smHi + drow + o, srcH + o, sz);
        cp16(smLo + drow + o, srcL + o, sz);
    }
}

// ---------------- persistent node GEMM: 512 thr, mat-split warps, 3-stage ----------------
#define NO_BIAS  0                               // 512
#define NO_WSHI  1024
#define NO_WSLO  (NO_WSHI + 128 * PK128 * 2)     // +34816
#define NO_WNHI  (NO_WSLO + 128 * PK128 * 2)
#define NO_A0    (NO_WNHI + 128 * PK128 * 2)
#define NO_SMEM  (NO_A0 + 3 * NO_STAGE)          // 209920

__global__ __launch_bounds__(512, 1) void k_mm_node(
    int wsel, const float* __restrict__ bias, float* __restrict__ Cself)
{
    extern __shared__ char sm[];
    uint32_t sb = smem_u32(sm);
    int tid = threadIdx.x;
    int lane = tid & 31, w = tid >> 5;
    int mat   = w & 1;            // 0 = self (3-term), 1 = support (2-term)
    int warpN = (w >> 1) & 3;
    int warpM = (w >> 3) & 1;

    if (tid < 128) ((float*)(sm + NO_BIAS))[tid] = bias[tid];
    {
        const uint4* whS = (const uint4*)(g_whi + (size_t)(2 * wsel) * 16384);
        const uint4* wlS = (const uint4*)(g_wlo + (size_t)(2 * wsel) * 16384);
        const uint4* whN = (const uint4*)(g_whi + (size_t)(2 * wsel + 1) * 16384);
        for (int idx = tid; idx < 2048; idx += 512) {
            int r = idx >> 4, u = idx & 15;
            uint32_t off = r * (PK128 * 2) + u * 16;
            *(uint4*)(sm + NO_WSHI + off) = whS[idx];
            *(uint4*)(sm + NO_WSLO + off) = wlS[idx];
            *(uint4*)(sm + NO_WNHI + off) = whN[idx];
        }
    }

    uint32_t stg[3] = { sb + NO_A0, sb + NO_A0 + NO_STAGE, sb + NO_A0 + 2 * NO_STAGE };
    const float* sbias = (const float*)(sm + NO_BIAS);

    uint32_t aRow = warpM * 32 + (lane & 15);
    uint32_t aColSel = (lane >> 4) * 8;
    uint32_t aOff0 = (aRow * PK128 + aColSel) * 2;
    uint32_t aOff1 = ((aRow + 16) * PK128 + aColSel) * 2;
    uint32_t bRow = warpN * 32 + (lane & 7);
    uint32_t bColSel = ((lane >> 3) & 1) * 8;
    uint32_t bOffBase = (bRow * PK128 + bColSel) * 2;
    uint32_t bHiBase = (mat ? (sb + NO_WNHI) : (sb + NO_WSHI)) + bOffBase;
    uint32_t bLoBase = (sb + NO_WSLO) + bOffBase;

    int g = gridDim.x;
    int t = blockIdx.x;
    int s = 0;
    issue_node_tile(t * 64, stg[0], stg[0] + NO_ASTG, tid);
    CP_COMMIT();
    issue_node_tile((t + g) * 64, stg[1], stg[1] + NO_ASTG, tid);
    CP_COMMIT();
    __syncthreads();

    while (t < NODE_TILES) {
        CP_WAIT1();
        __syncthreads();

        int s2i = (s >= 1) ? (s - 1) : 2;   // == (s+2)%3
        issue_node_tile((t + 2 * g) * 64, stg[s2i], stg[s2i] + NO_ASTG, tid);
        CP_COMMIT();

        float acc[2][4][4];
#pragma unroll
        for (int mt = 0; mt < 2; mt++)
#pragma unroll
            for (int nt = 0; nt < 4; nt++)
#pragma unroll
                for (int q = 0; q < 4; q++) acc[mt][nt][q] = 0.f;

        uint32_t asH = stg[s], asL = stg[s] + NO_ASTG;
#pragma unroll
        for (int ks = 0; ks < 8; ks++) {
            uint32_t kadd = ks * 32;
            uint32_t aH[2][4], aL[2][4];
            ldsm_x4(aH[0][0], aH[0][1], aH[0][2], aH[0][3], asH + aOff0 + kadd);
            ldsm_x4(aH[1][0], aH[1][1], aH[1][2], aH[1][3], asH + aOff1 + kadd);
            ldsm_x4(aL[0][0], aL[0][1], aL[0][2], aL[0][3], asL + aOff0 + kadd);
            ldsm_x4(aL[1][0], aL[1][1], aL[1][2], aL[1][3], asL + aOff1 + kadd);
#pragma unroll
            for (int nt = 0; nt < 4; nt++) {
                uint32_t bo = nt * 8 * PK128 * 2 + kadd;
                uint32_t bH[2];
                ldsm_x2(bH[0], bH[1], bHiBase + bo);
                mma16816(acc[0][nt], aH[0], bH);
                mma16816(acc[1][nt], aH[1], bH);
                mma16816(acc[0][nt], aL[0], bH);
                mma16816(acc[1][nt], aL[1], bH);
                if (!mat) {
                    uint32_t bL[2];
                    ldsm_x2(bL[0], bL[1], bLoBase + bo);
                    mma16816(acc[0][nt], aH[0], bL);
                    mma16816(acc[1][nt], aH[1], bL);
                }
            }
        }

        int base = t * 64;
        if (!mat) {
#pragma unroll
            for (int mt = 0; mt < 2; mt++) {
                int r0 = base + warpM * 32 + mt * 16 + (lane >> 2);
#pragma unroll
                for (int nt = 0; nt < 4; nt++) {
                    int c = warpN * 32 + nt * 8 + (lane & 3) * 2;
                    if (r0 < NN)
                        *(float2*)(Cself + (size_t)r0 * 128 + c) =
                            make_float2(acc[mt][nt][0] + sbias[c], acc[mt][nt][1] + sbias[c + 1]);
                    if (r0 + 8 < NN)
                        *(float2*)(Cself + (size_t)(r0 + 8) * 128 + c) =
                            make_float2(acc[mt][nt][2] + sbias[c], acc[mt][nt][3] + sbias[c + 1]);
                }
            }
        } else {
#pragma unroll
            for (int mt = 0; mt < 2; mt++) {
                int r0 = base + warpM * 32 + mt * 16 + (lane >> 2);
#pragma unroll
                for (int nt = 0; nt < 4; nt++) {
                    int c = warpN * 32 + nt * 8 + (lane & 3) * 2;
                    if (r0 < NN)
                        *(__half2*)(&g_suph[(size_t)r0 * 128 + c]) =
                            __halves2half2(__float2half_rn(acc[mt][nt][0]),
                                           __float2half_rn(acc[mt][nt][1]));
                    if (r0 + 8 < NN)
                        *(__half2*)(&g_suph[(size_t)(r0 + 8) * 128 + c]) =
                            __halves2half2(__float2half_rn(acc[mt][nt][2]),
                                           __float2half_rn(acc[mt][nt][3]));
                }
            }
        }
        t += g;
        s = (s + 1 == 3) ? 0 : (s + 1);
    }
}

// ---------------- persistent UV GEMM: U = Z@W1_top, V = Z@W1_bot (2-term, fp16 out) ----------------
#define NU_WTHI  0
#define NU_WBHI  (NU_WTHI + 128 * PK128 * 2)     // +34816
#define NU_A0    (NU_WBHI + 128 * PK128 * 2)
#define NU_SMEM  (NU_A0 + 3 * NO_STAGE)          // 174080

__global__ __launch_bounds__(512, 1) void k_mm_uv(__half* __restrict__ U, __half* __restrict__ V)
{
    extern __shared__ char sm[];
    uint32_t sb = smem_u32(sm);
    int tid = threadIdx.x;
    int lane = tid & 31, w = tid >> 5;
    int mat   = w & 1;            // 0 = U, 1 = V
    int warpN = (w >> 1) & 3;
    int warpM = (w >> 3) & 1;

    {
        const uint4* whT = (const uint4*)(g_whi + (size_t)6 * 16384);
        const uint4* whB = (const uint4*)(g_whi + (size_t)7 * 16384);
        for (int idx = tid; idx < 2048; idx += 512) {
            int r = idx >> 4, u = idx & 15;
            uint32_t off = r * (PK128 * 2) + u * 16;
            *(uint4*)(sm + NU_WTHI + off) = whT[idx];
            *(uint4*)(sm + NU_WBHI + off) = whB[idx];
        }
    }

    uint32_t stg[3] = { sb + NU_A0, sb + NU_A0 + NO_STAGE, sb + NU_A0 + 2 * NO_STAGE };

    uint32_t aRow = warpM * 32 + (lane & 15);
    uint32_t aColSel = (lane >> 4) * 8;
    uint32_t aOff0 = (aRow * PK128 + aColSel) * 2;
    uint32_t aOff1 = ((aRow + 16) * PK128 + aColSel) * 2;
    uint32_t bRow = warpN * 32 + (lane & 7);
    uint32_t bColSel = ((lane >> 3) & 1) * 8;
    uint32_t bOffBase = (bRow * PK128 + bColSel) * 2;
    uint32_t bHiBase = (mat ? (sb + NU_WBHI) : (sb + NU_WTHI)) + bOffBase;
    __half* Cout = mat ? V : U;

    int g = gridDim.x;
    int t = blockIdx.x;
    int s = 0;
    issue_node_tile(t * 64, stg[0], stg[0] + NO_ASTG, tid);
    CP_COMMIT();
    issue_node_tile((t + g) * 64, stg[1], stg[1] + NO_ASTG, tid);
    CP_COMMIT();
    __syncthreads();

    while (t < NODE_TILES) {
        CP_WAIT1();
        __syncthreads();

        int s2i = (s >= 1) ? (s - 1) : 2;
        issue_node_tile((t + 2 * g) * 64, stg[s2i], stg[s2i] + NO_ASTG, tid);
        CP_COMMIT();

        float acc[2][4][4];
#pragma unroll
        for (int mt = 0; mt < 2; mt++)
#pragma unroll
            for (int nt = 0; nt < 4; nt++)
#pragma unroll
                for (int q = 0; q < 4; q++) acc[mt][nt][q] = 0.f;

        uint32_t asH = stg[s], asL = stg[s] + NO_ASTG;
#pragma unroll
        for (int ks = 0; ks < 8; ks++) {
            uint32_t kadd = ks * 32;
            uint32_t aH[2][4], aL[2][4];
            ldsm_x4(aH[0][0], aH[0][1], aH[0][2], aH[0][3], asH + aOff0 + kadd);
            ldsm_x4(aH[1][0], aH[1][1], aH[1][2], aH[1][3], asH + aOff1 + kadd);
            ldsm_x4(aL[0][0], aL[0][1], aL[0][2], aL[0][3], asL + aOff0 + kadd);
            ldsm_x4(aL[1][0], aL[1][1], aL[1][2], aL[1][3], asL + aOff1 + kadd);
#pragma unroll
            for (int nt = 0; nt < 4; nt++) {
                uint32_t bo = nt * 8 * PK128 * 2 + kadd;
                uint32_t bH[2];
                ldsm_x2(bH[0], bH[1], bHiBase + bo);
                mma16816(acc[0][nt], aH[0], bH);
                mma16816(acc[1][nt], aH[1], bH);
                mma16816(acc[0][nt], aL[0], bH);
                mma16816(acc[1][nt], aL[1], bH);
            }
        }

        int base = t * 64;
#pragma unroll
        for (int mt = 0; mt < 2; mt++) {
            int r0 = base + warpM * 32 + mt * 16 + (lane >> 2);
#pragma unroll
            for (int nt = 0; nt < 4; nt++) {
                int c = warpN * 32 + nt * 8 + (lane & 3) * 2;
                if (r0 < NN)
                    *(__half2*)(Cout + (size_t)r0 * 128 + c) =
                        __halves2half2(__float2half_rn(acc[mt][nt][0]),
                                       __float2half_rn(acc[mt][nt][1]));
                if (r0 + 8 < NN)
                    *(__half2*)(Cout + (size_t)(r0 + 8) * 128 + c) =
                        __halves2half2(__float2half_rn(acc[mt][nt][2]),
                                       __float2half_rn(acc[mt][nt][3]));
            }
        }
        t += g;
        s = (s + 1 == 3) ? 0 : (s + 1);
    }
}

// ---------------- decoder gather (fp16 U,V): p = sigmoid(relu(U[x]+V[y]+b1) . w2 + b2) ----------------
__global__ __launch_bounds__(128) void k_dec_gather(
    const __half* __restrict__ U, const __half* __restrict__ V,
    const int* __restrict__ xidx, const int* __restrict__ yidx,
    const float* __restrict__ b1, const float* __restrict__ w2, const float* __restrict__ b2,
    float* __restrict__ p)
{
    int warp = threadIdx.x >> 5;
    int lane = threadIdx.x & 31;
    int pp = blockIdx.x * 4 + warp;
    if (pp >= NP) return;
    int xn = xidx[pp], yn = yidx[pp];
    uint2 uu = *(const uint2*)(U + (size_t)xn * 128 + lane * 4);
    uint2 vv = *(const uint2*)(V + (size_t)yn * 128 + lane * 4);
    float2 u01 = __half22float2(*reinterpret_cast<__half2*>(&uu.x));
    float2 u23 = __half22float2(*reinterpret_cast<__half2*>(&uu.y));
    float2 v01 = __half22float2(*reinterpret_cast<__half2*>(&vv.x));
    float2 v23 = __half22float2(*reinterpret_cast<__half2*>(&vv.y));
    float4 b4 = *(const float4*)(b1 + lane * 4);
    float4 w4 = *(const float4*)(w2 + lane * 4);
    float s = fmaxf(u01.x + v01.x + b4.x, 0.f) * w4.x
            + fmaxf(u01.y + v01.y + b4.y, 0.f) * w4.y
            + fmaxf(u23.x + v23.x + b4.z, 0.f) * w4.z
            + fmaxf(u23.y + v23.y + b4.w, 0.f) * w4.w;
#pragma unroll
    for (int off = 16; off > 0; off >>= 1) s += __shfl_down_sync(0xffffffffu, s, off);
    if (lane == 0) {
        s += b2[0];
        p[pp] = 1.f / (1.f + expf(-s));
    }
}

// ---------------- launch ----------------
extern "C" void kernel_launch(void* const* d_in, const int* in_sizes, int n_in,
                              void* d_out, int out_size) {
    const float* x     = (const float*)d_in[0];
    const int*   erow  = (const int*)  d_in[1];
    const int*   ecol  = (const int*)  d_in[2];
    const float* ew    = (const float*)d_in[3];
    const int*   xidx  = (const int*)  d_in[4];
    const int*   yidx  = (const int*)  d_in[5];
    const float* ws[3] = { (const float*)d_in[6],  (const float*)d_in[9],  (const float*)d_in[12] };
    const float* wn[3] = { (const float*)d_in[7],  (const float*)d_in[10], (const float*)d_in[13] };
    const float* bb[3] = { (const float*)d_in[8],  (const float*)d_in[11], (const float*)d_in[14] };
    const float* dw1 = (const float*)d_in[15];
    const float* db1 = (const float*)d_in[16];
    const float* dw2 = (const float*)d_in[17];
    const float* db2 = (const float*)d_in[18];

    float* out = (float*)d_out;
    float* p_out = out;            // [NP]
    float* z_out = out + NP;       // [NN*128]

    void* ptr;
    cudaGetSymbolAddress(&ptr, g_selfb);   float*  selfb_buf = (float*)ptr;
    cudaGetSymbolAddress(&ptr, g_suph);    __half* u_buf     = (__half*)ptr;  // U reuses suph
    cudaGetSymbolAddress(&ptr, g_vh);      __half* v_buf     = (__half*)ptr;

    int nsm = 148;
    cudaDeviceGetAttribute(&nsm, cudaDevAttrMultiProcessorCount, 0);

    cudaFuncSetAttribute(k_mm_node, cudaFuncAttributeMaxDynamicSharedMemorySize, NO_SMEM);
    cudaFuncSetAttribute(k_mm_uv,   cudaFuncAttributeMaxDynamicSharedMemorySize, NU_SMEM);

    // side stream for the CSR build (independent of converts + layer-1 GEMM)
    cudaStream_t s2;
    cudaStreamCreateWithFlags(&s2, cudaStreamNonBlocking);
    cudaEvent_t eFork, eJoin;
    cudaEventCreateWithFlags(&eFork, cudaEventDisableTiming);
    cudaEventCreateWithFlags(&eJoin, cudaEventDisableTiming);

    cudaEventRecord(eFork, 0);
    cudaStreamWaitEvent(s2, eFork, 0);

    const int aggGrid = (NN + 3) / 4;   // warp-per-node

    // main stream: converts + layer-1 GEMM (launch #4 overall = mm_node, for ncu)
    k_convert_x<<<(NN * 32 + 255) / 256, 256>>>(x);                                         // 1
    k_convert_weights<<<(W_TOTAL + 255) / 256, 256>>>(ws[0], wn[0], ws[1], wn[1], ws[2], wn[2], dw1); // 2
    k_zero_deg<<<(NN + 255) / 256, 256, 0, s2>>>();                                         // 3 (s2)
    k_mm_node<<<nsm, 512, NO_SMEM>>>(0, bb[0], selfb_buf);                                  // 4 <- profiled
    // CSR chain on s2
    k_count_deg<<<(NE + 255) / 256, 256, 0, s2>>>(erow);                                    // 5
    k_scan_part<<<NBLK, SCAN_B, 0, s2>>>();                                                 // 6
    k_scan_mid<<<1, 128, 0, s2>>>();                                                        // 7
    k_scan_final<<<NBLK, SCAN_B, 0, s2>>>();                                                // 8
    k_scatter_edges<<<(NE + 255) / 256, 256, 0, s2>>>(erow, ecol, ew);                      // 9
    cudaEventRecord(eJoin, s2);
    cudaStreamWaitEvent(0, eJoin, 0);

    k_aggregate<<<aggGrid, 128>>>(nullptr, 1, 0);                                           // 10
    k_mm_node<<<nsm, 512, NO_SMEM>>>(1, bb[1], selfb_buf);                                  // 11
    k_aggregate<<<aggGrid, 128>>>(nullptr, 1, 0);                                           // 12
    k_mm_node<<<nsm, 512, NO_SMEM>>>(2, bb[2], selfb_buf);                                  // 13
    k_aggregate<<<aggGrid, 128>>>(z_out, 0, 1);                                             // 14 (z + ahi/alo)
    // decoder: factored through W1, fp16 U/V
    k_mm_uv<<<nsm, 512, NU_SMEM>>>(u_buf, v_buf);                                           // 15
    k_dec_gather<<<(NP + 3) / 4, 128>>>(u_buf, v_buf, xidx, yidx, db1, dw2, db2, p_out);    // 16
}

// round 16
// speedup vs baseline: 1.2910x; 1.0101x over previous
#include <cuda_runtime.h>
#include <cuda_fp16.h>
#include <math.h>
#include <stdint.h>

#define NN 100000
#define NE 1600000
#define NP 500000
#define SCAN_B 1024
#define NBLK ((NN + SCAN_B - 1) / SCAN_B)   // 98

// ---------------- static device scratch ----------------
__device__ float  g_selfb[(size_t)NN * 128];
__device__ __half g_suph[(size_t)NN * 128];   // h @ Wn fp16; reused as U (fp16)
__device__ __half g_vh[(size_t)NN * 128];     // V (fp16)
__device__ __half g_ahi[(size_t)NN * 128];
__device__ __half g_alo[(size_t)NN * 128];
__device__ int   g_rowptr[NN + 1];
__device__ int   g_cursor[NN];
__device__ int   g_partial[NBLK];
__device__ int   g_blockoff[NBLK];
__device__ int   g_pcol[NE];
__device__ float g_pw[NE];
#define W_TOTAL (8 * 16384)
__device__ __half g_whi[W_TOTAL];
__device__ __half g_wlo[W_TOTAL];

#define PK128 136

// ---------------- helpers ----------------
__device__ __forceinline__ uint32_t smem_u32(const void* p) {
    uint32_t a;
    asm("{ .reg .u64 t; cvta.to.shared.u64 t, %1; cvt.u32.u64 %0, t; }" : "=r"(a) : "l"(p));
    return a;
}
__device__ __forceinline__ void ldsm_x4(uint32_t& r0, uint32_t& r1, uint32_t& r2, uint32_t& r3,
                                        uint32_t addr) {
    asm volatile("ldmatrix.sync.aligned.m8n8.x4.shared.b16 {%0,%1,%2,%3}, [%4];"
                 : "=r"(r0), "=r"(r1), "=r"(r2), "=r"(r3) : "r"(addr));
}
__device__ __forceinline__ void mma16816(float* c, const uint32_t* a, const uint32_t* b) {
    asm volatile("mma.sync.aligned.m16n8k16.row.col.f32.f16.f16.f32 "
                 "{%0,%1,%2,%3}, {%4,%5,%6,%7}, {%8,%9}, {%0,%1,%2,%3};"
                 : "+f"(c[0]), "+f"(c[1]), "+f"(c[2]), "+f"(c[3])
                 : "r"(a[0]), "r"(a[1]), "r"(a[2]), "r"(a[3]), "r"(b[0]), "r"(b[1]));
}
__device__ __forceinline__ void cp16(uint32_t dst, const void* src, unsigned sz) {
    asm volatile("cp.async.cg.shared.global [%0], [%1], 16, %2;"
                 :: "r"(dst), "l"(src), "r"(sz) : "memory");
}
#define CP_COMMIT() asm volatile("cp.async.commit_group;" ::: "memory")
#define CP_WAIT1()  asm volatile("cp.async.wait_group 1;" ::: "memory")

__device__ __forceinline__ void split1(float v, __half& h, __half& l) {
    h = __float2half_rn(v);
    l = __float2half_rn(v - __half2float(h));
}

// ---------------- CSR build ----------------
__global__ void k_zero_deg() {
    int i = blockIdx.x * blockDim.x + threadIdx.x;
    if (i < NN) g_cursor[i] = 0;
}
__global__ void k_count_deg(const int* __restrict__ row) {
    int e = blockIdx.x * blockDim.x + threadIdx.x;
    if (e < NE) atomicAdd(&g_cursor[row[e]], 1);
}
__global__ __launch_bounds__(SCAN_B) void k_scan_part() {
    __shared__ int sh[SCAN_B / 32];
    int t = threadIdx.x;
    int idx = blockIdx.x * SCAN_B + t;
    int v = (idx < NN) ? g_cursor[idx] : 0;
#pragma unroll
    for (int off = 16; off > 0; off >>= 1) v += __shfl_down_sync(0xffffffffu, v, off);
    if ((t & 31) == 0) sh[t >> 5] = v;
    __syncthreads();
    if (t < 32) {
        int s = (t < SCAN_B / 32) ? sh[t] : 0;
#pragma unroll
        for (int off = 16; off > 0; off >>= 1) s += __shfl_down_sync(0xffffffffu, s, off);
        if (t == 0) g_partial[blockIdx.x] = s;
    }
}
__global__ __launch_bounds__(128) void k_scan_mid() {
    __shared__ int sh[128];
    int t = threadIdx.x;
    int v = (t < NBLK) ? g_partial[t] : 0;
    sh[t] = v;
    __syncthreads();
#pragma unroll
    for (int off = 1; off < 128; off <<= 1) {
        int y = (t >= off) ? sh[t - off] : 0;
        __syncthreads();
        sh[t] += y;
        __syncthreads();
    }
    if (t < NBLK) g_blockoff[t] = sh[t] - v;
}
__global__ __launch_bounds__(SCAN_B) void k_scan_final() {
    __shared__ int sh[SCAN_B];
    int t = threadIdx.x;
    int idx = blockIdx.x * SCAN_B + t;
    int v = (idx < NN) ? g_cursor[idx] : 0;
    sh[t] = v;
    __syncthreads();
#pragma unroll
    for (int off = 1; off < SCAN_B; off <<= 1) {
        int y = (t >= off) ? sh[t - off] : 0;
        __syncthreads();
        sh[t] += y;
        __syncthreads();
    }
    if (idx < NN) {
        int incl = sh[t] + g_blockoff[blockIdx.x];
        g_rowptr[idx + 1] = incl;
        g_cursor[idx] = incl - v;
    }
    if (idx == 0) g_rowptr[0] = 0;
}
__global__ void k_scatter_edges(const int* __restrict__ row, const int* __restrict__ col,
                                const float* __restrict__ w) {
    int e = blockIdx.x * blockDim.x + threadIdx.x;
    if (e < NE) {
        int pos = atomicAdd(&g_cursor[row[e]], 1);
        g_pcol[pos] = col[e];
        g_pw[pos]   = w[e];
    }
}

// ---------------- converters ----------------
__global__ void k_convert_x(const float* __restrict__ x) {
    int i = blockIdx.x * blockDim.x + threadIdx.x;
    if (i < NN * 32) {
        float4 v = *(const float4*)(x + (size_t)i * 4);
        __half h0, h1, h2, h3, l0, l1, l2, l3;
        split1(v.x, h0, l0); split1(v.y, h1, l1);
        split1(v.z, h2, l2); split1(v.w, h3, l3);
        __half2 H01 = __halves2half2(h0, h1), H23 = __halves2half2(h2, h3);
        __half2 L01 = __halves2half2(l0, l1), L23 = __halves2half2(l2, l3);
        uint2 uh, ul;
        uh.x = *reinterpret_cast<unsigned*>(&H01); uh.y = *reinterpret_cast<unsigned*>(&H23);
        ul.x = *reinterpret_cast<unsigned*>(&L01); ul.y = *reinterpret_cast<unsigned*>(&L23);
        *(uint2*)(g_ahi + (size_t)i * 4) = uh;
        *(uint2*)(g_alo + (size_t)i * 4) = ul;
    }
}
__global__ void k_convert_weights(const float* w0, const float* w1_, const float* w2_,
                                  const float* w3, const float* w4, const float* w5,
                                  const float* wdec) {
    int idx = blockIdx.x * blockDim.x + threadIdx.x;
    if (idx >= W_TOTAL) return;
    int m = idx >> 14;
    int e = idx & 16383;
    int n = e >> 7, k = e & 127;
    float v;
    if (m < 6) {
        const float* W = (m == 0) ? w0 : (m == 1) ? w1_ : (m == 2) ? w2_
                       : (m == 3) ? w3 : (m == 4) ? w4 : w5;
        v = W[k * 128 + n];
    } else {
        v = wdec[((m - 6) * 128 + k) * 128 + n];
    }
    __half h, l;
    split1(v, h, l);
    g_whi[idx] = h;
    g_wlo[idx] = l;
}

// ---------------- neighbor aggregation: warp-per-node, 8B vector gathers ----------------
__global__ __launch_bounds__(128) void k_aggregate(float* __restrict__ outf, int relu, int writef) {
    int warp = threadIdx.x >> 5;
    int lane = threadIdx.x & 31;
    int node = blockIdx.x * 4 + warp;
    if (node >= NN) return;
    size_t base = (size_t)node * 128 + lane * 4;

    float4 sv = *(const float4*)(g_selfb + base);
    float a0 = sv.x, a1 = sv.y, a2 = sv.z, a3 = sv.w;

    int s = g_rowptr[node];
    int e = g_rowptr[node + 1];
    for (int i0 = s; i0 < e; i0 += 32) {
        int n = e - i0;
        if (n > 32) n = 32;
        int   c  = 0;
        float wv = 0.f;
        if (lane < n) { c = g_pcol[i0 + lane]; wv = g_pw[i0 + lane]; }
        for (int j = 0; j < n; j++) {
            int   cj = __shfl_sync(0xffffffffu, c, j);
            float wj = __shfl_sync(0xffffffffu, wv, j);
            uint2 hv = *(const uint2*)(g_suph + (size_t)cj * 128 + lane * 4);
            __half2 h01 = *reinterpret_cast<__half2*>(&hv.x);
            __half2 h23 = *reinterpret_cast<__half2*>(&hv.y);
            float2 f01 = __half22float2(h01);
            float2 f23 = __half22float2(h23);
            a0 += wj * f01.x; a1 += wj * f01.y;
            a2 += wj * f23.x; a3 += wj * f23.y;
        }
    }
    if (relu) {
        a0 = fmaxf(a0, 0.f); a1 = fmaxf(a1, 0.f);
        a2 = fmaxf(a2, 0.f); a3 = fmaxf(a3, 0.f);
    }
    if (writef) *(float4*)(outf + base) = make_float4(a0, a1, a2, a3);
    __half h0, h1, h2, h3, l0, l1, l2, l3;
    split1(a0, h0, l0); split1(a1, h1, l1);
    split1(a2, h2, l2); split1(a3, h3, l3);
    __half2 H01 = __halves2half2(h0, h1), H23 = __halves2half2(h2, h3);
    __half2 L01 = __halves2half2(l0, l1), L23 = __halves2half2(l2, l3);
    uint2 uh, ul;
    uh.x = *reinterpret_cast<unsigned*>(&H01); uh.y = *reinterpret_cast<unsigned*>(&H23);
    ul.x = *reinterpret_cast<unsigned*>(&L01); ul.y = *reinterpret_cast<unsigned*>(&L23);
    *(uint2*)(g_ahi + base) = uh;
    *(uint2*)(g_alo + base) = ul;
}

// ---------------- shared GEMM plumbing ----------------
#define NODE_TILES ((NN + 63) / 64)              // 1563
#define NO_ASTG  (64 * PK128 * 2)                // 17408
#define NO_STAGE (2 * NO_ASTG)                   // 34816 per stage (hi+lo)

__device__ __forceinline__ void issue_node_tile(int rowBase, uint32_t smHi, uint32_t smLo, int tid) {
    int r = tid >> 3;               // 0..63
    int u0 = (tid & 7) * 2;         // units 0..15
    long long gr = (long long)rowBase + r;
    unsigned sz = (gr < NN) ? 16u : 0u;
    long long grc = gr < NN ? gr : (NN - 1);
    const char* srcH = (const char*)g_ahi + grc * 256;
    const char* srcL = (const char*)g_alo + grc * 256;
    uint32_t drow = (uint32_t)r * (PK128 * 2);
#pragma unroll
    for (int q = 0; q < 2; q++) {
        uint32_t o = (u0 + q) * 16;
        cp16(smHi + drow + o, srcH + o, sz);
        cp16(smLo + drow + o, srcL + o, sz);
    }
}

// ---------------- persistent node GEMM: 512 thr, mat-split warps, 3-stage, x4 B-loads ----------------
#define NO_BIAS  0                               // 512
#define NO_WSHI  1024
#define NO_WSLO  (NO_WSHI + 128 * PK128 * 2)     // +34816
#define NO_WNHI  (NO_WSLO + 128 * PK128 * 2)
#define NO_A0    (NO_WNHI + 128 * PK128 * 2)
#define NO_SMEM  (NO_A0 + 3 * NO_STAGE)          // 209920

__global__ __launch_bounds__(512, 1) void k_mm_node(
    int wsel, const float* __restrict__ bias, float* __restrict__ Cself)
{
    extern __shared__ char sm[];
    uint32_t sb = smem_u32(sm);
    int tid = threadIdx.x;
    int lane = tid & 31, w = tid >> 5;
    int mat   = w & 1;            // 0 = self (3-term), 1 = support (2-term)
    int warpN = (w >> 1) & 3;
    int warpM = (w >> 3) & 1;

    if (tid < 128) ((float*)(sm + NO_BIAS))[tid] = bias[tid];
    {
        const uint4* whS = (const uint4*)(g_whi + (size_t)(2 * wsel) * 16384);
        const uint4* wlS = (const uint4*)(g_wlo + (size_t)(2 * wsel) * 16384);
        const uint4* whN = (const uint4*)(g_whi + (size_t)(2 * wsel + 1) * 16384);
        for (int idx = tid; idx < 2048; idx += 512) {
            int r = idx >> 4, u = idx & 15;
            uint32_t off = r * (PK128 * 2) + u * 16;
            *(uint4*)(sm + NO_WSHI + off) = whS[idx];
            *(uint4*)(sm + NO_WSLO + off) = wlS[idx];
            *(uint4*)(sm + NO_WNHI + off) = whN[idx];
        }
    }

    uint32_t stg[3] = { sb + NO_A0, sb + NO_A0 + NO_STAGE, sb + NO_A0 + 2 * NO_STAGE };
    const float* sbias = (const float*)(sm + NO_BIAS);

    uint32_t aRow = warpM * 32 + (lane & 15);
    uint32_t aColSel = (lane >> 4) * 8;
    uint32_t aOff0 = (aRow * PK128 + aColSel) * 2;
    uint32_t aOff1 = ((aRow + 16) * PK128 + aColSel) * 2;
    // x4 B addressing: lanes 0-7 rows n..n+7 col k; 8-15 col k+8; 16-23 rows n+8..n+15 col k; 24-31 col k+8
    uint32_t bRow4 = warpN * 32 + (lane & 7) + ((lane >> 4) << 3);
    uint32_t bColSel = ((lane >> 3) & 1) * 8;
    uint32_t bOffBase4 = (bRow4 * PK128 + bColSel) * 2;
    uint32_t bHiBase = (mat ? (sb + NO_WNHI) : (sb + NO_WSHI)) + bOffBase4;
    uint32_t bLoBase = (sb + NO_WSLO) + bOffBase4;

    int g = gridDim.x;
    int t = blockIdx.x;
    int s = 0;
    issue_node_tile(t * 64, stg[0], stg[0] + NO_ASTG, tid);
    CP_COMMIT();
    issue_node_tile((t + g) * 64, stg[1], stg[1] + NO_ASTG, tid);
    CP_COMMIT();
    __syncthreads();

    while (t < NODE_TILES) {
        CP_WAIT1();
        __syncthreads();

        int s2i = (s >= 1) ? (s - 1) : 2;   // == (s+2)%3
        issue_node_tile((t + 2 * g) * 64, stg[s2i], stg[s2i] + NO_ASTG, tid);
        CP_COMMIT();

        float acc[2][4][4];
#pragma unroll
        for (int mt = 0; mt < 2; mt++)
#pragma unroll
            for (int nt = 0; nt < 4; nt++)
#pragma unroll
                for (int q = 0; q < 4; q++) acc[mt][nt][q] = 0.f;

        uint32_t asH = stg[s], asL = stg[s] + NO_ASTG;
#pragma unroll
        for (int ks = 0; ks < 8; ks++) {
            uint32_t kadd = ks * 32;
            uint32_t aH[2][4], aL[2][4];
            ldsm_x4(aH[0][0], aH[0][1], aH[0][2], aH[0][3], asH + aOff0 + kadd);
            ldsm_x4(aH[1][0], aH[1][1], aH[1][2], aH[1][3], asH + aOff1 + kadd);
            ldsm_x4(aL[0][0], aL[0][1], aL[0][2], aL[0][3], asL + aOff0 + kadd);
            ldsm_x4(aL[1][0], aL[1][1], aL[1][2], aL[1][3], asL + aOff1 + kadd);
#pragma unroll
            for (int np = 0; np < 2; np++) {    // nt pairs {0,1}, {2,3}
                uint32_t bo = np * 16 * PK128 * 2 + kadd;
                uint32_t bH4[4];
                ldsm_x4(bH4[0], bH4[1], bH4[2], bH4[3], bHiBase + bo);
                int nt0 = np * 2, nt1 = np * 2 + 1;
                mma16816(acc[0][nt0], aH[0], bH4 + 0);
                mma16816(acc[1][nt0], aH[1], bH4 + 0);
                mma16816(acc[0][nt1], aH[0], bH4 + 2);
                mma16816(acc[1][nt1], aH[1], bH4 + 2);
                mma16816(acc[0][nt0], aL[0], bH4 + 0);
                mma16816(acc[1][nt0], aL[1], bH4 + 0);
                mma16816(acc[0][nt1], aL[0], bH4 + 2);
                mma16816(acc[1][nt1], aL[1], bH4 + 2);
                if (!mat) {
                    uint32_t bL4[4];
                    ldsm_x4(bL4[0], bL4[1], bL4[2], bL4[3], bLoBase + bo);
                    mma16816(acc[0][nt0], aH[0], bL4 + 0);
                    mma16816(acc[1][nt0], aH[1], bL4 + 0);
                    mma16816(acc[0][nt1], aH[0], bL4 + 2);
                    mma16816(acc[1][nt1], aH[1], bL4 + 2);
                }
            }
        }

        int base = t * 64;
        if (!mat) {
#pragma unroll
            for (int mt = 0; mt < 2; mt++) {
                int r0 = base + warpM * 32 + mt * 16 + (lane >> 2);
#pragma unroll
                for (int nt = 0; nt < 4; nt++) {
                    int c = warpN * 32 + nt * 8 + (lane & 3) * 2;
                    if (r0 < NN)
                        *(float2*)(Cself + (size_t)r0 * 128 + c) =
                            make_float2(acc[mt][nt][0] + sbias[c], acc[mt][nt][1] + sbias[c + 1]);
                    if (r0 + 8 < NN)
                        *(float2*)(Cself + (size_t)(r0 + 8) * 128 + c) =
                            make_float2(acc[mt][nt][2] + sbias[c], acc[mt][nt][3] + sbias[c + 1]);
                }
            }
        } else {
#pragma unroll
            for (int mt = 0; mt < 2; mt++) {
                int r0 = base + warpM * 32 + mt * 16 + (lane >> 2);
#pragma unroll
                for (int nt = 0; nt < 4; nt++) {
                    int c = warpN * 32 + nt * 8 + (lane & 3) * 2;
                    if (r0 < NN)
                        *(__half2*)(&g_suph[(size_t)r0 * 128 + c]) =
                            __halves2half2(__float2half_rn(acc[mt][nt][0]),
                                           __float2half_rn(acc[mt][nt][1]));
                    if (r0 + 8 < NN)
                        *(__half2*)(&g_suph[(size_t)(r0 + 8) * 128 + c]) =
                            __halves2half2(__float2half_rn(acc[mt][nt][2]),
                                           __float2half_rn(acc[mt][nt][3]));
                }
            }
        }
        t += g;
        s = (s + 1 == 3) ? 0 : (s + 1);
    }
}

// ---------------- persistent UV GEMM: U = Z@W1_top, V = Z@W1_bot (2-term, fp16 out, x4 B) ----------------
#define NU_WTHI  0
#define NU_WBHI  (NU_WTHI + 128 * PK128 * 2)     // +34816
#define NU_A0    (NU_WBHI + 128 * PK128 * 2)
#define NU_SMEM  (NU_A0 + 3 * NO_STAGE)          // 174080

__global__ __launch_bounds__(512, 1) void k_mm_uv(__half* __restrict__ U, __half* __restrict__ V)
{
    extern __shared__ char sm[];
    uint32_t sb = smem_u32(sm);
    int tid = threadIdx.x;
    int lane = tid & 31, w = tid >> 5;
    int mat   = w & 1;            // 0 = U, 1 = V
    int warpN = (w >> 1) & 3;
    int warpM = (w >> 3) & 1;

    {
        const uint4* whT = (const uint4*)(g_whi + (size_t)6 * 16384);
        const uint4* whB = (const uint4*)(g_whi + (size_t)7 * 16384);
        for (int idx = tid; idx < 2048; idx += 512) {
            int r = idx >> 4, u = idx & 15;
            uint32_t off = r * (PK128 * 2) + u * 16;
            *(uint4*)(sm + NU_WTHI + off) = whT[idx];
            *(uint4*)(sm + NU_WBHI + off) = whB[idx];
        }
    }

    uint32_t stg[3] = { sb + NU_A0, sb + NU_A0 + NO_STAGE, sb + NU_A0 + 2 * NO_STAGE };

    uint32_t aRow = warpM * 32 + (lane & 15);
    uint32_t aColSel = (lane >> 4) * 8;
    uint32_t aOff0 = (aRow * PK128 + aColSel) * 2;
    uint32_t aOff1 = ((aRow + 16) * PK128 + aColSel) * 2;
    uint32_t bRow4 = warpN * 32 + (lane & 7) + ((lane >> 4) << 3);
    uint32_t bColSel = ((lane >> 3) & 1) * 8;
    uint32_t bOffBase4 = (bRow4 * PK128 + bColSel) * 2;
    uint32_t bHiBase = (mat ? (sb + NU_WBHI) : (sb + NU_WTHI)) + bOffBase4;
    __half* Cout = mat ? V : U;

    int g = gridDim.x;
    int t = blockIdx.x;
    int s = 0;
    issue_node_tile(t * 64, stg[0], stg[0] + NO_ASTG, tid);
    CP_COMMIT();
    issue_node_tile((t + g) * 64, stg[1], stg[1] + NO_ASTG, tid);
    CP_COMMIT();
    __syncthreads();

    while (t < NODE_TILES) {
        CP_WAIT1();
        __syncthreads();

        int s2i = (s >= 1) ? (s - 1) : 2;
        issue_node_tile((t + 2 * g) * 64, stg[s2i], stg[s2i] + NO_ASTG, tid);
        CP_COMMIT();

        float acc[2][4][4];
#pragma unroll
        for (int mt = 0; mt < 2; mt++)
#pragma unroll
            for (int nt = 0; nt < 4; nt++)
#pragma unroll
                for (int q = 0; q < 4; q++) acc[mt][nt][q] = 0.f;

        uint32_t asH = stg[s], asL = stg[s] + NO_ASTG;
#pragma unroll
        for (int ks = 0; ks < 8; ks++) {
            uint32_t kadd = ks * 32;
            uint32_t aH[2][4], aL[2][4];
            ldsm_x4(aH[0][0], aH[0][1], aH[0][2], aH[0][3], asH + aOff0 + kadd);
            ldsm_x4(aH[1][0], aH[1][1], aH[1][2], aH[1][3], asH + aOff1 + kadd);
            ldsm_x4(aL[0][0], aL[0][1], aL[0][2], aL[0][3], asL + aOff0 + kadd);
            ldsm_x4(aL[1][0], aL[1][1], aL[1][2], aL[1][3], asL + aOff1 + kadd);
#pragma unroll
            for (int np = 0; np < 2; np++) {
                uint32_t bo = np * 16 * PK128 * 2 + kadd;
                uint32_t bH4[4];
                ldsm_x4(bH4[0], bH4[1], bH4[2], bH4[3], bHiBase + bo);
                int nt0 = np * 2, nt1 = np * 2 + 1;
                mma16816(acc[0][nt0], aH[0], bH4 + 0);
                mma16816(acc[1][nt0], aH[1], bH4 + 0);
                mma16816(acc[0][nt1], aH[0], bH4 + 2);
                mma16816(acc[1][nt1], aH[1], bH4 + 2);
                mma16816(acc[0][nt0], aL[0], bH4 + 0);
                mma16816(acc[1][nt0], aL[1], bH4 + 0);
                mma16816(acc[0][nt1], aL[0], bH4 + 2);
                mma16816(acc[1][nt1], aL[1], bH4 + 2);
            }
        }

        int base = t * 64;
#pragma unroll
        for (int mt = 0; mt < 2; mt++) {
            int r0 = base + warpM * 32 + mt * 16 + (lane >> 2);
#pragma unroll
            for (int nt = 0; nt < 4; nt++) {
                int c = warpN * 32 + nt * 8 + (lane & 3) * 2;
                if (r0 < NN)
                    *(__half2*)(Cout + (size_t)r0 * 128 + c) =
                        __halves2half2(__float2half_rn(acc[mt][nt][0]),
                                       __float2half_rn(acc[mt][nt][1]));
                if (r0 + 8 < NN)
                    *(__half2*)(Cout + (size_t)(r0 + 8) * 128 + c) =
                        __halves2half2(__float2half_rn(acc[mt][nt][2]),
                                       __float2half_rn(acc[mt][nt][3]));
            }
        }
        t += g;
        s = (s + 1 == 3) ? 0 : (s + 1);
    }
}

// ---------------- decoder gather (fp16 U,V) ----------------
__global__ __launch_bounds__(128) void k_dec_gather(
    const __half* __restrict__ U, const __half* __restrict__ V,
    const int* __restrict__ xidx, const int* __restrict__ yidx,
    const float* __restrict__ b1, const float* __restrict__ w2, const float* __restrict__ b2,
    float* __restrict__ p)
{
    int warp = threadIdx.x >> 5;
    int lane = threadIdx.x & 31;
    int pp = blockIdx.x * 4 + warp;
    if (pp >= NP) return;
    int xn = xidx[pp], yn = yidx[pp];
    uint2 uu = *(const uint2*)(U + (size_t)xn * 128 + lane * 4);
    uint2 vv = *(const uint2*)(V + (size_t)yn * 128 + lane * 4);
    float2 u01 = __half22float2(*reinterpret_cast<__half2*>(&uu.x));
    float2 u23 = __half22float2(*reinterpret_cast<__half2*>(&uu.y));
    float2 v01 = __half22float2(*reinterpret_cast<__half2*>(&vv.x));
    float2 v23 = __half22float2(*reinterpret_cast<__half2*>(&vv.y));
    float4 b4 = *(const float4*)(b1 + lane * 4);
    float4 w4 = *(const float4*)(w2 + lane * 4);
    float s = fmaxf(u01.x + v01.x + b4.x, 0.f) * w4.x
            + fmaxf(u01.y + v01.y + b4.y, 0.f) * w4.y
            + fmaxf(u23.x + v23.x + b4.z, 0.f) * w4.z
            + fmaxf(u23.y + v23.y + b4.w, 0.f) * w4.w;
#pragma unroll
    for (int off = 16; off > 0; off >>= 1) s += __shfl_down_sync(0xffffffffu, s, off);
    if (lane == 0) {
        s += b2[0];
        p[pp] = 1.f / (1.f + expf(-s));
    }
}

// ---------------- launch ----------------
extern "C" void kernel_launch(void* const* d_in, const int* in_sizes, int n_in,
                              void* d_out, int out_size) {
    const float* x     = (const float*)d_in[0];
    const int*   erow  = (const int*)  d_in[1];
    const int*   ecol  = (const int*)  d_in[2];
    const float* ew    = (const float*)d_in[3];
    const int*   xidx  = (const int*)  d_in[4];
    const int*   yidx  = (const int*)  d_in[5];
    const float* ws[3] = { (const float*)d_in[6],  (const float*)d_in[9],  (const float*)d_in[12] };
    const float* wn[3] = { (const float*)d_in[7],  (const float*)d_in[10], (const float*)d_in[13] };
    const float* bb[3] = { (const float*)d_in[8],  (const float*)d_in[11], (const float*)d_in[14] };
    const float* dw1 = (const float*)d_in[15];
    const float* db1 = (const float*)d_in[16];
    const float* dw2 = (const float*)d_in[17];
    const float* db2 = (const float*)d_in[18];

    float* out = (float*)d_out;
    float* p_out = out;            // [NP]
    float* z_out = out + NP;       // [NN*128]

    void* ptr;
    cudaGetSymbolAddress(&ptr, g_selfb);   float*  selfb_buf = (float*)ptr;
    cudaGetSymbolAddress(&ptr, g_suph);    __half* u_buf     = (__half*)ptr;  // U reuses suph
    cudaGetSymbolAddress(&ptr, g_vh);      __half* v_buf     = (__half*)ptr;

    int nsm = 148;
    cudaDeviceGetAttribute(&nsm, cudaDevAttrMultiProcessorCount, 0);

    cudaFuncSetAttribute(k_mm_node, cudaFuncAttributeMaxDynamicSharedMemorySize, NO_SMEM);
    cudaFuncSetAttribute(k_mm_uv,   cudaFuncAttributeMaxDynamicSharedMemorySize, NU_SMEM);

    // side stream for the CSR build (independent of converts + layer-1 GEMM)
    cudaStream_t s2;
    cudaStreamCreateWithFlags(&s2, cudaStreamNonBlocking);
    cudaEvent_t eFork, eJoin;
    cudaEventCreateWithFlags(&eFork, cudaEventDisableTiming);
    cudaEventCreateWithFlags(&eJoin, cudaEventDisableTiming);

    cudaEventRecord(eFork, 0);
    cudaStreamWaitEvent(s2, eFork, 0);

    const int aggGrid = (NN + 3) / 4;   // warp-per-node

    // main stream: converts + layer-1 GEMM (launch #4 overall = mm_node, for ncu)
    k_convert_x<<<(NN * 32 + 255) / 256, 256>>>(x);                                         // 1
    k_convert_weights<<<(W_TOTAL + 255) / 256, 256>>>(ws[0], wn[0], ws[1], wn[1], ws[2], wn[2], dw1); // 2
    k_zero_deg<<<(NN + 255) / 256, 256, 0, s2>>>();                                         // 3 (s2)
    k_mm_node<<<nsm, 512, NO_SMEM>>>(0, bb[0], selfb_buf);                                  // 4 <- profiled
    // CSR chain on s2
    k_count_deg<<<(NE + 255) / 256, 256, 0, s2>>>(erow);                                    // 5
    k_scan_part<<<NBLK, SCAN_B, 0, s2>>>();                                                 // 6
    k_scan_mid<<<1, 128, 0, s2>>>();                                                        // 7
    k_scan_final<<<NBLK, SCAN_B, 0, s2>>>();                                                // 8
    k_scatter_edges<<<(NE + 255) / 256, 256, 0, s2>>>(erow, ecol, ew);                      // 9
    cudaEventRecord(eJoin, s2);
    cudaStreamWaitEvent(0, eJoin, 0);

    k_aggregate<<<aggGrid, 128>>>(nullptr, 1, 0);                                           // 10
    k_mm_node<<<nsm, 512, NO_SMEM>>>(1, bb[1], selfb_buf);                                  // 11
    k_aggregate<<<aggGrid, 128>>>(nullptr, 1, 0);                                           // 12
    k_mm_node<<<nsm, 512, NO_SMEM>>>(2, bb[2], selfb_buf);                                  // 13
    k_aggregate<<<aggGrid, 128>>>(z_out, 0, 1);                                             // 14 (z + ahi/alo)
    // decoder: factored through W1, fp16 U/V
    k_mm_uv<<<nsm, 512, NU_SMEM>>>(u_buf, v_buf);                                           // 15
    k_dec_gather<<<(NP + 3) / 4, 128>>>(u_buf, v_buf, xidx, yidx, db1, dw2, db2, p_out);    // 16
}